// round 3
// baseline (speedup 1.0000x reference)
#include <cuda_runtime.h>
#include <cstdint>

// NN upsample x2, NHWC fp32: (8,128,128,256) -> (8,256,256,256)
// One thread per input float8 (32B): 1x LDG.256, 4x STG.256.
// A warp (32 threads x 32B = 1024B) covers exactly one pixel's channel run,
// so every store instruction is one fully-contiguous 1024B warp transaction.

static constexpr int B  = 8;
static constexpr int H  = 128;
static constexpr int W  = 128;
static constexpr int C8 = 256 / 8;   // 32 float8 per pixel
static constexpr int WO = W * 2;     // 256
static constexpr long long N_IN8 = (long long)B * H * W * C8;  // 4,194,304

struct __align__(32) f8 { float4 a, b; };

__device__ __forceinline__ f8 ldg256(const f8* p) {
    f8 v;
    asm volatile("ld.global.nc.v8.f32 {%0,%1,%2,%3,%4,%5,%6,%7}, [%8];"
                 : "=f"(v.a.x), "=f"(v.a.y), "=f"(v.a.z), "=f"(v.a.w),
                   "=f"(v.b.x), "=f"(v.b.y), "=f"(v.b.z), "=f"(v.b.w)
                 : "l"(p));
    return v;
}

__device__ __forceinline__ void stg256(f8* p, const f8& v) {
    asm volatile("st.global.v8.f32 [%0], {%1,%2,%3,%4,%5,%6,%7,%8};"
                 :: "l"(p),
                    "f"(v.a.x), "f"(v.a.y), "f"(v.a.z), "f"(v.a.w),
                    "f"(v.b.x), "f"(v.b.y), "f"(v.b.z), "f"(v.b.w)
                 : "memory");
}

__global__ __launch_bounds__(256, 8)
void upsample2x_kernel(const f8* __restrict__ in, f8* __restrict__ out)
{
    long long idx = (long long)blockIdx.x * blockDim.x + threadIdx.x;
    if (idx >= N_IN8) return;

    // idx = ((b*H + h)*W + w)*C8 + c8
    int c8 = (int)(idx & (C8 - 1));          // C8 = 32
    long long t = idx >> 5;                  // (b*H + h)*W + w
    int w = (int)(t & (W - 1));              // W = 128
    long long bh = t >> 7;                   // b*H + h

    f8 v = ldg256(in + idx);

    // Output base for pixel (2h, 2w) in [B, 2H, 2W, C8]:
    long long o = ((2ll * bh) * WO + 2ll * w) * C8 + c8;
    long long rowStride = (long long)WO * C8;   // 8192

    stg256(out + o,                  v);  // (2h,   2w)
    stg256(out + o + C8,             v);  // (2h,   2w+1)
    stg256(out + o + rowStride,      v);  // (2h+1, 2w)
    stg256(out + o + rowStride + C8, v);  // (2h+1, 2w+1)
}

extern "C" void kernel_launch(void* const* d_in, const int* in_sizes, int n_in,
                              void* d_out, int out_size)
{
    const f8* in  = (const f8*)d_in[0];
    f8*       out = (f8*)d_out;

    const int threads = 256;
    const long long blocks = (N_IN8 + threads - 1) / threads;  // 16384
    upsample2x_kernel<<<(unsigned)blocks, threads>>>(in, out);
}